// round 1
// baseline (speedup 1.0000x reference)
#include <cuda_runtime.h>
#include <math.h>

#define D_MODEL   1024
#define T_SEQ     2048
#define B_SZ      4
#define N_HEADS   16
#define HEAD_DIM  64
#define M_ROWS    (B_SZ * T_SEQ)   // 8192
#define QKV_N     (3 * D_MODEL)    // 3072

// Scratch (no cudaMalloc allowed): qkv = 100.7 MB, att = 33.6 MB
__device__ float g_qkv[(size_t)M_ROWS * QKV_N];
__device__ float g_att[(size_t)M_ROWS * D_MODEL];

// ---------------------------------------------------------------------------
// Tiled fp32 SGEMM: C[M,N] = A[M,K] @ B[K,N], all row-major.
// 64x64 block tile, K-panel 16, 256 threads, 4x4 microtile per thread.
// M,N divisible by 64; K divisible by 16 (true for all our shapes).
// ---------------------------------------------------------------------------
__global__ __launch_bounds__(256) void sgemm64(const float* __restrict__ A,
                                               const float* __restrict__ B,
                                               float* __restrict__ C,
                                               int M, int N, int K) {
    __shared__ float As[16][64];   // k-major (transposed) -> conflict-free reads
    __shared__ float Bs[16][64];
    const int t  = threadIdx.x;
    const int tx = t & 15;
    const int ty = t >> 4;
    const int m0 = blockIdx.y * 64;
    const int n0 = blockIdx.x * 64;

    // load mapping
    const int ar  = t >> 2;        // 0..63  (A row within tile)
    const int ak4 = (t & 3) * 4;   // 0..12  (A k offset, float4)
    const int bk  = t >> 4;        // 0..15  (B k within panel)
    const int bc4 = (t & 15) * 4;  // 0..60  (B col offset, float4)

    float acc[4][4] = {};

    for (int k0 = 0; k0 < K; k0 += 16) {
        float4 a = *(const float4*)(A + (size_t)(m0 + ar) * K + k0 + ak4);
        float4 b = *(const float4*)(B + (size_t)(k0 + bk) * N + n0 + bc4);
        __syncthreads();           // prior iteration finished reading smem
        As[ak4 + 0][ar] = a.x;
        As[ak4 + 1][ar] = a.y;
        As[ak4 + 2][ar] = a.z;
        As[ak4 + 3][ar] = a.w;
        *(float4*)&Bs[bk][bc4] = b;
        __syncthreads();

#pragma unroll
        for (int kk = 0; kk < 16; ++kk) {
            float av[4], bv[4];
#pragma unroll
            for (int i = 0; i < 4; ++i) av[i] = As[kk][ty * 4 + i];
#pragma unroll
            for (int j = 0; j < 4; ++j) bv[j] = Bs[kk][tx * 4 + j];
#pragma unroll
            for (int i = 0; i < 4; ++i)
#pragma unroll
                for (int j = 0; j < 4; ++j)
                    acc[i][j] = fmaf(av[i], bv[j], acc[i][j]);
        }
    }

#pragma unroll
    for (int i = 0; i < 4; ++i) {
        float4 o = make_float4(acc[i][0], acc[i][1], acc[i][2], acc[i][3]);
        *(float4*)(C + (size_t)(m0 + ty * 4 + i) * N + n0 + tx * 4) = o;
    }
}

// ---------------------------------------------------------------------------
// Flash attention (causal, fp32). One block per (q-tile of 64 rows, b*h).
// Br = Bc = 64, Dh = 64. Online softmax, only kt <= qtile tiles visited.
// Dynamic smem: Qs, Ks, Vs, Ps each [64][65] (pad avoids bank conflicts).
// ---------------------------------------------------------------------------
__global__ __launch_bounds__(256) void flash_attn(const float* __restrict__ qkv,
                                                  float* __restrict__ att) {
    extern __shared__ float sh[];
    float* Qs = sh;                 // [64][65]
    float* Ks = Qs + 64 * 65;
    float* Vs = Ks + 64 * 65;
    float* Ps = Vs + 64 * 65;

    const int qtile = blockIdx.x;            // 0..31
    const int bh    = blockIdx.y;            // 0..63
    const int b     = bh >> 4;
    const int h     = bh & 15;
    const int t     = threadIdx.x;
    const int tx    = t & 15;
    const int ty    = t >> 4;

    const int   rowbase = b * T_SEQ;
    const int   qcol    = h * HEAD_DIM;      // within 3072: q:+0, k:+1024, v:+2048
    const float scale   = 0.125f;            // 1/sqrt(64)

    // load Q tile (pre-scaled)
    {
        const int r  = t >> 4;               // 0..15
        const int d4 = (t & 15) * 4;
#pragma unroll
        for (int u = 0; u < 4; ++u) {
            const int rr = r + u * 16;
            float4 v = *(const float4*)(qkv + (size_t)(rowbase + qtile * 64 + rr) * QKV_N + qcol + d4);
            Qs[rr * 65 + d4 + 0] = v.x * scale;
            Qs[rr * 65 + d4 + 1] = v.y * scale;
            Qs[rr * 65 + d4 + 2] = v.z * scale;
            Qs[rr * 65 + d4 + 3] = v.w * scale;
        }
    }

    float m_i[4], l_i[4], acc[4][4] = {};
#pragma unroll
    for (int i = 0; i < 4; ++i) { m_i[i] = -1e30f; l_i[i] = 0.0f; }

    for (int kt = 0; kt <= qtile; ++kt) {
        // stage K/V tile through registers, then into smem
        const int r  = t >> 4;
        const int d4 = (t & 15) * 4;
        float4 kreg[4], vreg[4];
#pragma unroll
        for (int u = 0; u < 4; ++u) {
            const int rr = r + u * 16;
            const size_t rowoff = (size_t)(rowbase + kt * 64 + rr) * QKV_N;
            kreg[u] = *(const float4*)(qkv + rowoff + D_MODEL     + qcol + d4);
            vreg[u] = *(const float4*)(qkv + rowoff + 2 * D_MODEL + qcol + d4);
        }
        __syncthreads();   // previous iter done reading Ks/Vs/Ps
#pragma unroll
        for (int u = 0; u < 4; ++u) {
            const int rr = r + u * 16;
            Ks[rr * 65 + d4 + 0] = kreg[u].x;
            Ks[rr * 65 + d4 + 1] = kreg[u].y;
            Ks[rr * 65 + d4 + 2] = kreg[u].z;
            Ks[rr * 65 + d4 + 3] = kreg[u].w;
            Vs[rr * 65 + d4 + 0] = vreg[u].x;
            Vs[rr * 65 + d4 + 1] = vreg[u].y;
            Vs[rr * 65 + d4 + 2] = vreg[u].z;
            Vs[rr * 65 + d4 + 3] = vreg[u].w;
        }
        __syncthreads();

        // S = Q K^T (4x4 microtile per thread)
        float s[4][4] = {};
#pragma unroll
        for (int kk = 0; kk < 64; ++kk) {
            float qv[4], kv[4];
#pragma unroll
            for (int i = 0; i < 4; ++i) qv[i] = Qs[(ty * 4 + i) * 65 + kk];
#pragma unroll
            for (int j = 0; j < 4; ++j) kv[j] = Ks[(tx * 4 + j) * 65 + kk];
#pragma unroll
            for (int i = 0; i < 4; ++i)
#pragma unroll
                for (int j = 0; j < 4; ++j)
                    s[i][j] = fmaf(qv[i], kv[j], s[i][j]);
        }

        // causal mask (only diagonal tile)
        if (kt == qtile) {
#pragma unroll
            for (int i = 0; i < 4; ++i)
#pragma unroll
                for (int j = 0; j < 4; ++j)
                    if (tx * 4 + j > ty * 4 + i) s[i][j] = -1e30f;
        }

        // online softmax update per row (16 tx-lanes cooperate per row)
#pragma unroll
        for (int i = 0; i < 4; ++i) {
            float mx = s[i][0];
#pragma unroll
            for (int j = 1; j < 4; ++j) mx = fmaxf(mx, s[i][j]);
#pragma unroll
            for (int off = 8; off > 0; off >>= 1)
                mx = fmaxf(mx, __shfl_xor_sync(0xffffffffu, mx, off, 32));

            const float mnew = fmaxf(m_i[i], mx);
            const float corr = __expf(m_i[i] - mnew);
            float rowsum = 0.0f;
#pragma unroll
            for (int j = 0; j < 4; ++j) {
                const float p = __expf(s[i][j] - mnew);
                s[i][j] = p;
                rowsum += p;
            }
#pragma unroll
            for (int off = 8; off > 0; off >>= 1)
                rowsum += __shfl_xor_sync(0xffffffffu, rowsum, off, 32);

            l_i[i] = l_i[i] * corr + rowsum;
            m_i[i] = mnew;
#pragma unroll
            for (int j = 0; j < 4; ++j) acc[i][j] *= corr;
        }

        // publish P, then acc += P @ V
#pragma unroll
        for (int i = 0; i < 4; ++i)
#pragma unroll
            for (int j = 0; j < 4; ++j)
                Ps[(ty * 4 + i) * 65 + tx * 4 + j] = s[i][j];
        __syncthreads();

#pragma unroll
        for (int c = 0; c < 64; ++c) {
            float pv[4], vv[4];
#pragma unroll
            for (int i = 0; i < 4; ++i) pv[i] = Ps[(ty * 4 + i) * 65 + c];
#pragma unroll
            for (int j = 0; j < 4; ++j) vv[j] = Vs[c * 65 + tx * 4 + j];
#pragma unroll
            for (int i = 0; i < 4; ++i)
#pragma unroll
                for (int j = 0; j < 4; ++j)
                    acc[i][j] = fmaf(pv[i], vv[j], acc[i][j]);
        }
    }

    // epilogue: normalize and store to [8192, 1024] (head-contiguous layout)
#pragma unroll
    for (int i = 0; i < 4; ++i) {
        const float inv_l = 1.0f / l_i[i];
        float4 o = make_float4(acc[i][0] * inv_l, acc[i][1] * inv_l,
                               acc[i][2] * inv_l, acc[i][3] * inv_l);
        *(float4*)(att + (size_t)(rowbase + qtile * 64 + ty * 4 + i) * D_MODEL
                       + h * HEAD_DIM + tx * 4) = o;
    }
}

// ---------------------------------------------------------------------------
extern "C" void kernel_launch(void* const* d_in, const int* in_sizes, int n_in,
                              void* d_out, int out_size) {
    const float* x     = (const float*)d_in[0];   // [4,2048,1024]
    const float* W_qkv = (const float*)d_in[1];   // [1024,3072]
    const float* W_out = (const float*)d_in[2];   // [1024,1024]
    float*       out   = (float*)d_out;           // [4,2048,1024]

    float* qkv; float* att;
    cudaGetSymbolAddress((void**)&qkv, g_qkv);
    cudaGetSymbolAddress((void**)&att, g_att);

    const int smem_attn = 4 * 64 * 65 * (int)sizeof(float);  // 66560 B
    cudaFuncSetAttribute(flash_attn, cudaFuncAttributeMaxDynamicSharedMemorySize, smem_attn);

    // 1) qkv = x @ W_qkv   (8192 x 1024 @ 1024 x 3072)
    sgemm64<<<dim3(QKV_N / 64, M_ROWS / 64), 256>>>(x, W_qkv, qkv, M_ROWS, QKV_N, D_MODEL);

    // 2) causal flash attention -> att [8192, 1024]
    flash_attn<<<dim3(T_SEQ / 64, B_SZ * N_HEADS), 256, smem_attn>>>(qkv, att);

    // 3) out = att @ W_out  (8192 x 1024 @ 1024 x 1024)
    sgemm64<<<dim3(D_MODEL / 64, M_ROWS / 64), 256>>>(att, W_out, out, M_ROWS, D_MODEL, D_MODEL);
}

// round 4
// speedup vs baseline: 1.7572x; 1.7572x over previous
#include <cuda_runtime.h>
#include <cuda_bf16.h>
#include <math.h>
#include <cstdint>

#define D_MODEL   1024
#define T_SEQ     2048
#define B_SZ      4
#define N_HEADS   16
#define HEAD_DIM  64
#define M_ROWS    8192
#define QKV_N     3072

// Scratch (no cudaMalloc allowed)
__device__ float          g_qkv[(size_t)M_ROWS * QKV_N];        // fp32 for SIMT attention
__device__ __nv_bfloat16  g_x_hi[(size_t)M_ROWS * D_MODEL];
__device__ __nv_bfloat16  g_x_lo[(size_t)M_ROWS * D_MODEL];
__device__ __nv_bfloat16  g_wqkv_hi[(size_t)QKV_N * D_MODEL];   // [N,K] transposed
__device__ __nv_bfloat16  g_wqkv_lo[(size_t)QKV_N * D_MODEL];
__device__ __nv_bfloat16  g_wout_hi[(size_t)D_MODEL * D_MODEL];
__device__ __nv_bfloat16  g_wout_lo[(size_t)D_MODEL * D_MODEL];
__device__ __nv_bfloat16  g_att_hi[(size_t)M_ROWS * D_MODEL];
__device__ __nv_bfloat16  g_att_lo[(size_t)M_ROWS * D_MODEL];

__device__ __forceinline__ uint32_t smem_u32(const void* p) {
    uint32_t a;
    asm("{ .reg .u64 t; cvta.to.shared.u64 t, %1; cvt.u32.u64 %0, t; }" : "=r"(a) : "l"(p));
    return a;
}
__device__ __forceinline__ void split_bf(float x, __nv_bfloat16& h, __nv_bfloat16& l) {
    h = __float2bfloat16_rn(x);
    l = __float2bfloat16_rn(x - __bfloat162float(h));
}

#define LDSM4(r, addr) \
    asm volatile("ldmatrix.sync.aligned.m8n8.x4.shared.b16 {%0,%1,%2,%3}, [%4];" \
        : "=r"((r)[0]), "=r"((r)[1]), "=r"((r)[2]), "=r"((r)[3]) : "r"(addr))

#define MMA_BF16(d, a, b) \
    asm volatile("mma.sync.aligned.m16n8k16.row.col.f32.bf16.bf16.f32 " \
        "{%0,%1,%2,%3}, {%4,%5,%6,%7}, {%8,%9}, {%0,%1,%2,%3};" \
        : "+f"((d)[0]), "+f"((d)[1]), "+f"((d)[2]), "+f"((d)[3]) \
        : "r"((a)[0]), "r"((a)[1]), "r"((a)[2]), "r"((a)[3]), "r"((b)[0]), "r"((b)[1]))

// ---------------------------------------------------------------------------
// split_x: fp32 -> (hi, lo) bf16
// ---------------------------------------------------------------------------
__global__ void split_x_kernel(const float4* __restrict__ x,
                               __nv_bfloat16* __restrict__ hi,
                               __nv_bfloat16* __restrict__ lo, int n4) {
    const int i = blockIdx.x * 256 + threadIdx.x;
    if (i >= n4) return;
    float4 v = x[i];
    __nv_bfloat16 h[4], l[4];
    split_bf(v.x, h[0], l[0]); split_bf(v.y, h[1], l[1]);
    split_bf(v.z, h[2], l[2]); split_bf(v.w, h[3], l[3]);
    __nv_bfloat162* hp = reinterpret_cast<__nv_bfloat162*>(hi) + 2 * i;
    __nv_bfloat162* lp = reinterpret_cast<__nv_bfloat162*>(lo) + 2 * i;
    hp[0] = __nv_bfloat162(h[0], h[1]); hp[1] = __nv_bfloat162(h[2], h[3]);
    lp[0] = __nv_bfloat162(l[0], l[1]); lp[1] = __nv_bfloat162(l[2], l[3]);
}

// ---------------------------------------------------------------------------
// transpose + split: Wt_hi/lo[n*Kr + k] = split(W[k*Nc + n])
// ---------------------------------------------------------------------------
__global__ void transpose_split(const float* __restrict__ W,
                                __nv_bfloat16* __restrict__ Wth,
                                __nv_bfloat16* __restrict__ Wtl,
                                int Kr, int Nc) {
    __shared__ float tile[32][33];
    const int bx = blockIdx.x * 32, by = blockIdx.y * 32;
    const int tx = threadIdx.x, ty = threadIdx.y;
#pragma unroll
    for (int u = 0; u < 32; u += 8)
        tile[ty + u][tx] = W[(size_t)(by + ty + u) * Nc + bx + tx];
    __syncthreads();
#pragma unroll
    for (int u = 0; u < 32; u += 8) {
        __nv_bfloat16 h, l;
        split_bf(tile[tx][ty + u], h, l);
        const size_t o = (size_t)(bx + ty + u) * Kr + by + tx;
        Wth[o] = h; Wtl[o] = l;
    }
}

// ---------------------------------------------------------------------------
// 3-MMA split-bf16 GEMM: C[M,N] = A[M,K] @ Bt[N,K]^T   (fp32-accurate to ~1e-5)
// CTA 128x128, 4 warps 64x64, K-panel 32, double-buffered cp.async.
// SMEM bf16 rows padded to 80B: 16B-aligned, conflict-free ldmatrix (20 mod 32).
// ---------------------------------------------------------------------------
#define PANEL    32
#define RSTRIDE  80                     // bytes per 32-bf16 row (64B data + pad)
#define TILE_B   (128 * RSTRIDE)        // 10240 per operand tile
#define STAGE_B  (4 * TILE_B)           // Ah, Al, Bh, Bl

__global__ __launch_bounds__(128, 1) void bf16_gemm(const __nv_bfloat16* __restrict__ Ah,
                                                    const __nv_bfloat16* __restrict__ Al,
                                                    const __nv_bfloat16* __restrict__ Bh,
                                                    const __nv_bfloat16* __restrict__ Bl,
                                                    float* __restrict__ C,
                                                    int M, int N, int K) {
    extern __shared__ char sm[];
    const uint32_t base = smem_u32(sm);

    const int t = threadIdx.x;
    const int wid = t >> 5, lane = t & 31;
    const int m0 = blockIdx.y * 128, n0 = blockIdx.x * 128;
    const int wm = (wid >> 1) * 64, wn = (wid & 1) * 64;
    const int NKI = K / PANEL;

    // cp.async mapping: thread -> (row, 16B seg); 4 rows per tile, 4 tiles
    const int rg = t >> 2, sg = t & 3;              // rg 0..31, sg 0..3
    const uint32_t s_off = (uint32_t)(rg * RSTRIDE + sg * 16);

#define LOAD_STAGE(i, s) do { \
        const size_t _k0 = (size_t)(i) * PANEL + sg * 8; \
        const uint32_t _st = base + (s) * STAGE_B + s_off; \
        _Pragma("unroll") \
        for (int _u = 0; _u < 4; ++_u) { \
            const int _r = rg + _u * 32; \
            const uint32_t _so = _st + _u * 32 * RSTRIDE; \
            asm volatile("cp.async.cg.shared.global [%0], [%1], 16;" \
                :: "r"(_so),              "l"(Ah + (size_t)(m0 + _r) * K + _k0) : "memory"); \
            asm volatile("cp.async.cg.shared.global [%0], [%1], 16;" \
                :: "r"(_so + TILE_B),     "l"(Al + (size_t)(m0 + _r) * K + _k0) : "memory"); \
            asm volatile("cp.async.cg.shared.global [%0], [%1], 16;" \
                :: "r"(_so + 2 * TILE_B), "l"(Bh + (size_t)(n0 + _r) * K + _k0) : "memory"); \
            asm volatile("cp.async.cg.shared.global [%0], [%1], 16;" \
                :: "r"(_so + 3 * TILE_B), "l"(Bl + (size_t)(n0 + _r) * K + _k0) : "memory"); \
        } \
        asm volatile("cp.async.commit_group;" ::: "memory"); \
    } while (0)

    // ldmatrix offsets (within an operand tile)
    uint32_t aoff[4], boff[4];
#pragma unroll
    for (int mt = 0; mt < 4; ++mt)
        aoff[mt] = (uint32_t)((wm + mt * 16 + (lane & 15)) * RSTRIDE + (lane >> 4) * 16);
#pragma unroll
    for (int p = 0; p < 4; ++p)
        boff[p] = (uint32_t)((wn + p * 16 + ((lane >> 4) << 3) + (lane & 7)) * RSTRIDE
                             + ((lane >> 3) & 1) * 16);

    float acc[4][8][4];
#pragma unroll
    for (int i = 0; i < 4; ++i)
#pragma unroll
        for (int j = 0; j < 8; ++j)
#pragma unroll
            for (int r = 0; r < 4; ++r) acc[i][j][r] = 0.0f;

    LOAD_STAGE(0, 0);

    for (int i = 0; i < NKI; ++i) {
        if (i + 1 < NKI) {
            LOAD_STAGE(i + 1, (i + 1) & 1);
            asm volatile("cp.async.wait_group 1;" ::: "memory");
        } else {
            asm volatile("cp.async.wait_group 0;" ::: "memory");
        }
        __syncthreads();

        const uint32_t sAh = base + (i & 1) * STAGE_B;
        const uint32_t sAl = sAh + TILE_B;
        const uint32_t sBh = sAh + 2 * TILE_B;
        const uint32_t sBl = sAh + 3 * TILE_B;

#pragma unroll
        for (int ks = 0; ks < 2; ++ks) {            // two k16 steps per panel
            uint32_t ah[4][4], al[4][4];
#pragma unroll
            for (int mt = 0; mt < 4; ++mt) {
                LDSM4(ah[mt], sAh + aoff[mt] + ks * 32);
                LDSM4(al[mt], sAl + aoff[mt] + ks * 32);
            }
#pragma unroll
            for (int p = 0; p < 4; ++p) {
                uint32_t bh[4], bl[4];
                LDSM4(bh, sBh + boff[p] + ks * 32);
                LDSM4(bl, sBl + boff[p] + ks * 32);
#pragma unroll
                for (int mt = 0; mt < 4; ++mt) {
#pragma unroll
                    for (int j = 0; j < 2; ++j) {   // n8 = 2p + j
                        const int n8 = 2 * p + j;
                        MMA_BF16(acc[mt][n8], ah[mt], &bh[j * 2]);
                        MMA_BF16(acc[mt][n8], ah[mt], &bl[j * 2]);
                        MMA_BF16(acc[mt][n8], al[mt], &bh[j * 2]);
                    }
                }
            }
        }
        __syncthreads();
    }

    const int r_lo = lane >> 2, c_lo = (lane & 3) * 2;
#pragma unroll
    for (int mt = 0; mt < 4; ++mt) {
        const int row = m0 + wm + mt * 16 + r_lo;
#pragma unroll
        for (int n8 = 0; n8 < 8; ++n8) {
            const int col = n0 + wn + n8 * 8 + c_lo;
            *(float2*)(C + (size_t)row * N + col) =
                make_float2(acc[mt][n8][0], acc[mt][n8][1]);
            *(float2*)(C + (size_t)(row + 8) * N + col) =
                make_float2(acc[mt][n8][2], acc[mt][n8][3]);
        }
    }
#undef LOAD_STAGE
}

// ---------------------------------------------------------------------------
// Flash attention (causal, fp32 SIMT). Epilogue now writes split bf16.
// ---------------------------------------------------------------------------
__global__ __launch_bounds__(256) void flash_attn(const float* __restrict__ qkv,
                                                  __nv_bfloat16* __restrict__ att_hi,
                                                  __nv_bfloat16* __restrict__ att_lo) {
    extern __shared__ float sh[];
    float* Qs = sh;
    float* Ks = Qs + 64 * 65;
    float* Vs = Ks + 64 * 65;
    float* Ps = Vs + 64 * 65;

    const int qtile = blockIdx.x;
    const int bh    = blockIdx.y;
    const int b     = bh >> 4;
    const int h     = bh & 15;
    const int t     = threadIdx.x;
    const int tx    = t & 15;
    const int ty    = t >> 4;

    const int   rowbase = b * T_SEQ;
    const int   qcol    = h * HEAD_DIM;
    const float scale   = 0.125f;

    {
        const int r  = t >> 4;
        const int d4 = (t & 15) * 4;
#pragma unroll
        for (int u = 0; u < 4; ++u) {
            const int rr = r + u * 16;
            float4 v = *(const float4*)(qkv + (size_t)(rowbase + qtile * 64 + rr) * QKV_N + qcol + d4);
            Qs[rr * 65 + d4 + 0] = v.x * scale;
            Qs[rr * 65 + d4 + 1] = v.y * scale;
            Qs[rr * 65 + d4 + 2] = v.z * scale;
            Qs[rr * 65 + d4 + 3] = v.w * scale;
        }
    }

    float m_i[4], l_i[4], acc[4][4] = {};
#pragma unroll
    for (int i = 0; i < 4; ++i) { m_i[i] = -1e30f; l_i[i] = 0.0f; }

    for (int kt = 0; kt <= qtile; ++kt) {
        const int r  = t >> 4;
        const int d4 = (t & 15) * 4;
        float4 kreg[4], vreg[4];
#pragma unroll
        for (int u = 0; u < 4; ++u) {
            const int rr = r + u * 16;
            const size_t rowoff = (size_t)(rowbase + kt * 64 + rr) * QKV_N;
            kreg[u] = *(const float4*)(qkv + rowoff + D_MODEL     + qcol + d4);
            vreg[u] = *(const float4*)(qkv + rowoff + 2 * D_MODEL + qcol + d4);
        }
        __syncthreads();
#pragma unroll
        for (int u = 0; u < 4; ++u) {
            const int rr = r + u * 16;
            Ks[rr * 65 + d4 + 0] = kreg[u].x;
            Ks[rr * 65 + d4 + 1] = kreg[u].y;
            Ks[rr * 65 + d4 + 2] = kreg[u].z;
            Ks[rr * 65 + d4 + 3] = kreg[u].w;
            Vs[rr * 65 + d4 + 0] = vreg[u].x;
            Vs[rr * 65 + d4 + 1] = vreg[u].y;
            Vs[rr * 65 + d4 + 2] = vreg[u].z;
            Vs[rr * 65 + d4 + 3] = vreg[u].w;
        }
        __syncthreads();

        float s[4][4] = {};
#pragma unroll
        for (int kk = 0; kk < 64; ++kk) {
            float qv[4], kv[4];
#pragma unroll
            for (int i = 0; i < 4; ++i) qv[i] = Qs[(ty * 4 + i) * 65 + kk];
#pragma unroll
            for (int j = 0; j < 4; ++j) kv[j] = Ks[(tx * 4 + j) * 65 + kk];
#pragma unroll
            for (int i = 0; i < 4; ++i)
#pragma unroll
                for (int j = 0; j < 4; ++j)
                    s[i][j] = fmaf(qv[i], kv[j], s[i][j]);
        }

        if (kt == qtile) {
#pragma unroll
            for (int i = 0; i < 4; ++i)
#pragma unroll
                for (int j = 0; j < 4; ++j)
                    if (tx * 4 + j > ty * 4 + i) s[i][j] = -1e30f;
        }

#pragma unroll
        for (int i = 0; i < 4; ++i) {
            float mx = s[i][0];
#pragma unroll
            for (int j = 1; j < 4; ++j) mx = fmaxf(mx, s[i][j]);
#pragma unroll
            for (int off = 8; off > 0; off >>= 1)
                mx = fmaxf(mx, __shfl_xor_sync(0xffffffffu, mx, off, 32));

            const float mnew = fmaxf(m_i[i], mx);
            const float corr = __expf(m_i[i] - mnew);
            float rowsum = 0.0f;
#pragma unroll
            for (int j = 0; j < 4; ++j) {
                const float p = __expf(s[i][j] - mnew);
                s[i][j] = p;
                rowsum += p;
            }
#pragma unroll
            for (int off = 8; off > 0; off >>= 1)
                rowsum += __shfl_xor_sync(0xffffffffu, rowsum, off, 32);

            l_i[i] = l_i[i] * corr + rowsum;
            m_i[i] = mnew;
#pragma unroll
            for (int j = 0; j < 4; ++j) acc[i][j] *= corr;
        }

#pragma unroll
        for (int i = 0; i < 4; ++i)
#pragma unroll
            for (int j = 0; j < 4; ++j)
                Ps[(ty * 4 + i) * 65 + tx * 4 + j] = s[i][j];
        __syncthreads();

#pragma unroll
        for (int c = 0; c < 64; ++c) {
            float pv[4], vv[4];
#pragma unroll
            for (int i = 0; i < 4; ++i) pv[i] = Ps[(ty * 4 + i) * 65 + c];
#pragma unroll
            for (int j = 0; j < 4; ++j) vv[j] = Vs[c * 65 + tx * 4 + j];
#pragma unroll
            for (int i = 0; i < 4; ++i)
#pragma unroll
                for (int j = 0; j < 4; ++j)
                    acc[i][j] = fmaf(pv[i], vv[j], acc[i][j]);
        }
    }

#pragma unroll
    for (int i = 0; i < 4; ++i) {
        const float inv_l = 1.0f / l_i[i];
        __nv_bfloat16 h4[4], l4[4];
#pragma unroll
        for (int j = 0; j < 4; ++j) split_bf(acc[i][j] * inv_l, h4[j], l4[j]);
        const size_t o = (size_t)(rowbase + qtile * 64 + ty * 4 + i) * D_MODEL
                       + h * HEAD_DIM + tx * 4;
        __nv_bfloat162* hp = reinterpret_cast<__nv_bfloat162*>(att_hi + o);
        __nv_bfloat162* lp = reinterpret_cast<__nv_bfloat162*>(att_lo + o);
        hp[0] = __nv_bfloat162(h4[0], h4[1]); hp[1] = __nv_bfloat162(h4[2], h4[3]);
        lp[0] = __nv_bfloat162(l4[0], l4[1]); lp[1] = __nv_bfloat162(l4[2], l4[3]);
    }
}

// ---------------------------------------------------------------------------
extern "C" void kernel_launch(void* const* d_in, const int* in_sizes, int n_in,
                              void* d_out, int out_size) {
    const float* x     = (const float*)d_in[0];
    const float* W_qkv = (const float*)d_in[1];
    const float* W_out = (const float*)d_in[2];
    float*       out   = (float*)d_out;

    float* qkv;
    __nv_bfloat16 *xh, *xl, *wqh, *wql, *woh, *wol, *ath, *atl;
    cudaGetSymbolAddress((void**)&qkv, g_qkv);
    cudaGetSymbolAddress((void**)&xh,  g_x_hi);
    cudaGetSymbolAddress((void**)&xl,  g_x_lo);
    cudaGetSymbolAddress((void**)&wqh, g_wqkv_hi);
    cudaGetSymbolAddress((void**)&wql, g_wqkv_lo);
    cudaGetSymbolAddress((void**)&woh, g_wout_hi);
    cudaGetSymbolAddress((void**)&wol, g_wout_lo);
    cudaGetSymbolAddress((void**)&ath, g_att_hi);
    cudaGetSymbolAddress((void**)&atl, g_att_lo);

    const int smem_gemm = 2 * STAGE_B;                        // 81920
    const int smem_attn = 4 * 64 * 65 * (int)sizeof(float);
    cudaFuncSetAttribute(bf16_gemm, cudaFuncAttributeMaxDynamicSharedMemorySize, smem_gemm);
    cudaFuncSetAttribute(flash_attn, cudaFuncAttributeMaxDynamicSharedMemorySize, smem_attn);

    // prepare split operands
    split_x_kernel<<<(M_ROWS * D_MODEL / 4 + 255) / 256, 256>>>((const float4*)x, xh, xl, M_ROWS * D_MODEL / 4);
    transpose_split<<<dim3(QKV_N / 32, D_MODEL / 32), dim3(32, 8)>>>(W_qkv, wqh, wql, D_MODEL, QKV_N);
    transpose_split<<<dim3(D_MODEL / 32, D_MODEL / 32), dim3(32, 8)>>>(W_out, woh, wol, D_MODEL, D_MODEL);

    // 1) qkv = x @ W_qkv
    bf16_gemm<<<dim3(QKV_N / 128, M_ROWS / 128), 128, smem_gemm>>>(xh, xl, wqh, wql, qkv, M_ROWS, QKV_N, D_MODEL);

    // 2) causal flash attention (writes split bf16 att)
    flash_attn<<<dim3(T_SEQ / 64, B_SZ * N_HEADS), 256, smem_attn>>>(qkv, ath, atl);

    // 3) out = att @ W_out
    bf16_gemm<<<dim3(D_MODEL / 128, M_ROWS / 128), 128, smem_gemm>>>(ath, atl, woh, wol, out, M_ROWS, D_MODEL, D_MODEL);
}

// round 5
// speedup vs baseline: 3.2249x; 1.8353x over previous
#include <cuda_runtime.h>
#include <cuda_bf16.h>
#include <math.h>
#include <cstdint>

#define D_MODEL   1024
#define T_SEQ     2048
#define B_SZ      4
#define N_HEADS   16
#define HEAD_DIM  64
#define M_ROWS    8192
#define QKV_N     3072

// Scratch (no cudaMalloc allowed)
__device__ __nv_bfloat16  g_qkv_hi[(size_t)M_ROWS * QKV_N];
__device__ __nv_bfloat16  g_qkv_lo[(size_t)M_ROWS * QKV_N];
__device__ __nv_bfloat16  g_x_hi[(size_t)M_ROWS * D_MODEL];
__device__ __nv_bfloat16  g_x_lo[(size_t)M_ROWS * D_MODEL];
__device__ __nv_bfloat16  g_wqkv_hi[(size_t)QKV_N * D_MODEL];
__device__ __nv_bfloat16  g_wqkv_lo[(size_t)QKV_N * D_MODEL];
__device__ __nv_bfloat16  g_wout_hi[(size_t)D_MODEL * D_MODEL];
__device__ __nv_bfloat16  g_wout_lo[(size_t)D_MODEL * D_MODEL];
__device__ __nv_bfloat16  g_att_hi[(size_t)M_ROWS * D_MODEL];
__device__ __nv_bfloat16  g_att_lo[(size_t)M_ROWS * D_MODEL];

__device__ __forceinline__ uint32_t smem_u32(const void* p) {
    uint32_t a;
    asm("{ .reg .u64 t; cvta.to.shared.u64 t, %1; cvt.u32.u64 %0, t; }" : "=r"(a) : "l"(p));
    return a;
}
__device__ __forceinline__ void split_bf(float x, __nv_bfloat16& h, __nv_bfloat16& l) {
    h = __float2bfloat16_rn(x);
    l = __float2bfloat16_rn(x - __bfloat162float(h));
}
// split pair (a,b) -> hi bf16x2, lo bf16x2 (a in low half)
__device__ __forceinline__ void split2(float a, float b, uint32_t& h, uint32_t& l) {
    __nv_bfloat16 ha, la, hb, lb;
    split_bf(a, ha, la); split_bf(b, hb, lb);
    __nv_bfloat162 hv(ha, hb), lv(la, lb);
    h = *reinterpret_cast<uint32_t*>(&hv);
    l = *reinterpret_cast<uint32_t*>(&lv);
}

#define LDSM4(r, addr) \
    asm volatile("ldmatrix.sync.aligned.m8n8.x4.shared.b16 {%0,%1,%2,%3}, [%4];" \
        : "=r"((r)[0]), "=r"((r)[1]), "=r"((r)[2]), "=r"((r)[3]) : "r"(addr))
#define LDSM4T(r, addr) \
    asm volatile("ldmatrix.sync.aligned.m8n8.x4.trans.shared.b16 {%0,%1,%2,%3}, [%4];" \
        : "=r"((r)[0]), "=r"((r)[1]), "=r"((r)[2]), "=r"((r)[3]) : "r"(addr))

#define MMA_BF16(d, a, b) \
    asm volatile("mma.sync.aligned.m16n8k16.row.col.f32.bf16.bf16.f32 " \
        "{%0,%1,%2,%3}, {%4,%5,%6,%7}, {%8,%9}, {%0,%1,%2,%3};" \
        : "+f"((d)[0]), "+f"((d)[1]), "+f"((d)[2]), "+f"((d)[3]) \
        : "r"((a)[0]), "r"((a)[1]), "r"((a)[2]), "r"((a)[3]), "r"((b)[0]), "r"((b)[1]))

#define CP16(dst, src) \
    asm volatile("cp.async.cg.shared.global [%0], [%1], 16;" :: "r"(dst), "l"(src) : "memory")
#define CP_COMMIT() asm volatile("cp.async.commit_group;" ::: "memory")

// ---------------------------------------------------------------------------
__global__ void split_x_kernel(const float4* __restrict__ x,
                               __nv_bfloat16* __restrict__ hi,
                               __nv_bfloat16* __restrict__ lo, int n4) {
    const int i = blockIdx.x * 256 + threadIdx.x;
    if (i >= n4) return;
    float4 v = x[i];
    uint32_t h0, l0, h1, l1;
    split2(v.x, v.y, h0, l0); split2(v.z, v.w, h1, l1);
    uint32_t* hp = reinterpret_cast<uint32_t*>(hi) + 2 * i;
    uint32_t* lp = reinterpret_cast<uint32_t*>(lo) + 2 * i;
    hp[0] = h0; hp[1] = h1; lp[0] = l0; lp[1] = l1;
}

// transpose + split (+optional scale on first scale_lim output rows)
__global__ void transpose_split(const float* __restrict__ W,
                                __nv_bfloat16* __restrict__ Wth,
                                __nv_bfloat16* __restrict__ Wtl,
                                int Kr, int Nc, int scale_lim, float scale) {
    __shared__ float tile[32][33];
    const int bx = blockIdx.x * 32, by = blockIdx.y * 32;
    const int tx = threadIdx.x, ty = threadIdx.y;
#pragma unroll
    for (int u = 0; u < 32; u += 8)
        tile[ty + u][tx] = W[(size_t)(by + ty + u) * Nc + bx + tx];
    __syncthreads();
#pragma unroll
    for (int u = 0; u < 32; u += 8) {
        const int n = bx + ty + u;
        float v = tile[tx][ty + u];
        if (n < scale_lim) v *= scale;
        __nv_bfloat16 h, l;
        split_bf(v, h, l);
        const size_t o = (size_t)n * Kr + by + tx;
        Wth[o] = h; Wtl[o] = l;
    }
}

// ---------------------------------------------------------------------------
// 3-MMA split-bf16 GEMM. Output either fp32 C, or split bf16 (Chi/Clo).
// ---------------------------------------------------------------------------
#define PANEL    32
#define RSTRIDE  80
#define TILE_B   (128 * RSTRIDE)
#define STAGE_B  (4 * TILE_B)

__global__ __launch_bounds__(128, 1) void bf16_gemm(const __nv_bfloat16* __restrict__ Ah,
                                                    const __nv_bfloat16* __restrict__ Al,
                                                    const __nv_bfloat16* __restrict__ Bh,
                                                    const __nv_bfloat16* __restrict__ Bl,
                                                    float* __restrict__ C,
                                                    __nv_bfloat16* __restrict__ Chi,
                                                    __nv_bfloat16* __restrict__ Clo,
                                                    int M, int N, int K) {
    extern __shared__ char sm[];
    const uint32_t base = smem_u32(sm);

    const int t = threadIdx.x;
    const int wid = t >> 5, lane = t & 31;
    const int m0 = blockIdx.y * 128, n0 = blockIdx.x * 128;
    const int wm = (wid >> 1) * 64, wn = (wid & 1) * 64;
    const int NKI = K / PANEL;

    const int rg = t >> 2, sg = t & 3;
    const uint32_t s_off = (uint32_t)(rg * RSTRIDE + sg * 16);

#define LOAD_STAGE(i, s) do { \
        const size_t _k0 = (size_t)(i) * PANEL + sg * 8; \
        const uint32_t _st = base + (s) * STAGE_B + s_off; \
        _Pragma("unroll") \
        for (int _u = 0; _u < 4; ++_u) { \
            const int _r = rg + _u * 32; \
            const uint32_t _so = _st + _u * 32 * RSTRIDE; \
            CP16(_so,              Ah + (size_t)(m0 + _r) * K + _k0); \
            CP16(_so + TILE_B,     Al + (size_t)(m0 + _r) * K + _k0); \
            CP16(_so + 2 * TILE_B, Bh + (size_t)(n0 + _r) * K + _k0); \
            CP16(_so + 3 * TILE_B, Bl + (size_t)(n0 + _r) * K + _k0); \
        } \
        CP_COMMIT(); \
    } while (0)

    uint32_t aoff[4], boff[4];
#pragma unroll
    for (int mt = 0; mt < 4; ++mt)
        aoff[mt] = (uint32_t)((wm + mt * 16 + (lane & 15)) * RSTRIDE + (lane >> 4) * 16);
#pragma unroll
    for (int p = 0; p < 4; ++p)
        boff[p] = (uint32_t)((wn + p * 16 + ((lane >> 4) << 3) + (lane & 7)) * RSTRIDE
                             + ((lane >> 3) & 1) * 16);

    float acc[4][8][4];
#pragma unroll
    for (int i = 0; i < 4; ++i)
#pragma unroll
        for (int j = 0; j < 8; ++j)
#pragma unroll
            for (int r = 0; r < 4; ++r) acc[i][j][r] = 0.0f;

    LOAD_STAGE(0, 0);

    for (int i = 0; i < NKI; ++i) {
        if (i + 1 < NKI) {
            LOAD_STAGE(i + 1, (i + 1) & 1);
            asm volatile("cp.async.wait_group 1;" ::: "memory");
        } else {
            asm volatile("cp.async.wait_group 0;" ::: "memory");
        }
        __syncthreads();

        const uint32_t sAh = base + (i & 1) * STAGE_B;
        const uint32_t sAl = sAh + TILE_B;
        const uint32_t sBh = sAh + 2 * TILE_B;
        const uint32_t sBl = sAh + 3 * TILE_B;

#pragma unroll
        for (int ks = 0; ks < 2; ++ks) {
            uint32_t ah[4][4], al[4][4];
#pragma unroll
            for (int mt = 0; mt < 4; ++mt) {
                LDSM4(ah[mt], sAh + aoff[mt] + ks * 32);
                LDSM4(al[mt], sAl + aoff[mt] + ks * 32);
            }
#pragma unroll
            for (int p = 0; p < 4; ++p) {
                uint32_t bh[4], bl[4];
                LDSM4(bh, sBh + boff[p] + ks * 32);
                LDSM4(bl, sBl + boff[p] + ks * 32);
#pragma unroll
                for (int mt = 0; mt < 4; ++mt) {
#pragma unroll
                    for (int j = 0; j < 2; ++j) {
                        const int n8 = 2 * p + j;
                        MMA_BF16(acc[mt][n8], ah[mt], &bh[j * 2]);
                        MMA_BF16(acc[mt][n8], ah[mt], &bl[j * 2]);
                        MMA_BF16(acc[mt][n8], al[mt], &bh[j * 2]);
                    }
                }
            }
        }
        __syncthreads();
    }

    const int r_lo = lane >> 2, c_lo = (lane & 3) * 2;
#pragma unroll
    for (int mt = 0; mt < 4; ++mt) {
        const int row = m0 + wm + mt * 16 + r_lo;
#pragma unroll
        for (int n8 = 0; n8 < 8; ++n8) {
            const int col = n0 + wn + n8 * 8 + c_lo;
            if (C) {
                *(float2*)(C + (size_t)row * N + col) =
                    make_float2(acc[mt][n8][0], acc[mt][n8][1]);
                *(float2*)(C + (size_t)(row + 8) * N + col) =
                    make_float2(acc[mt][n8][2], acc[mt][n8][3]);
            } else {
                uint32_t h, l;
                split2(acc[mt][n8][0], acc[mt][n8][1], h, l);
                *(uint32_t*)(Chi + (size_t)row * N + col) = h;
                *(uint32_t*)(Clo + (size_t)row * N + col) = l;
                split2(acc[mt][n8][2], acc[mt][n8][3], h, l);
                *(uint32_t*)(Chi + (size_t)(row + 8) * N + col) = h;
                *(uint32_t*)(Clo + (size_t)(row + 8) * N + col) = l;
            }
        }
    }
#undef LOAD_STAGE
}

// ---------------------------------------------------------------------------
// Tensor-core flash attention (causal, split bf16, 3-MMA).
// 256 thr / 8 warps; q-tile 128 (1 m16/warp); k-tile 128; double-buffered K/V.
// ---------------------------------------------------------------------------
#define FAS    144                      // smem row stride (64 bf16 + pad)
#define FTILE  (128 * FAS)              // 18432
#define KVST   (4 * FTILE)              // Kh,Kl,Vh,Vl per stage

__global__ __launch_bounds__(256, 1) void flash_attn_tc(
    const __nv_bfloat16* __restrict__ qkvh,
    const __nv_bfloat16* __restrict__ qkvl,
    __nv_bfloat16* __restrict__ att_hi,
    __nv_bfloat16* __restrict__ att_lo) {
    extern __shared__ char sm[];
    const uint32_t base  = smem_u32(sm);        // KV stages: 2 * KVST
    const uint32_t qbase = base + 2 * KVST;     // Qh, Ql

    const int qi = (int)gridDim.x - 1 - (int)blockIdx.x;   // big tiles first
    const int bh = blockIdx.y;
    const int b  = bh >> 4, h = bh & 15;
    const int t  = threadIdx.x;
    const int wid = t >> 5, lane = t & 31;

    const int rowQ0 = b * T_SEQ + qi * 128;
    const int colQ = h * HEAD_DIM;
    const int colK = D_MODEL + h * HEAD_DIM;
    const int colV = 2 * D_MODEL + h * HEAD_DIM;

    // ---- load mapping: rg 0..31, sg 0..7 (16B), 4 rows per matrix per thread
    const int rg = t >> 3, sg = t & 7;
    const uint32_t ls_off = (uint32_t)(rg * FAS + sg * 16);

#define LOADKV(kt, s) do { \
        const uint32_t _st = base + (s) * KVST + ls_off; \
        _Pragma("unroll") \
        for (int _u = 0; _u < 4; ++_u) { \
            const int _r = rg + _u * 32; \
            const size_t _row = (size_t)(b * T_SEQ + (kt) * 128 + _r) * QKV_N; \
            const uint32_t _so = _st + _u * 32 * FAS; \
            CP16(_so,             qkvh + _row + colK + sg * 8); \
            CP16(_so + FTILE,     qkvl + _row + colK + sg * 8); \
            CP16(_so + 2 * FTILE, qkvh + _row + colV + sg * 8); \
            CP16(_so + 3 * FTILE, qkvl + _row + colV + sg * 8); \
        } \
        CP_COMMIT(); \
    } while (0)

    // ---- prologue: Q group, then KV(0)
    {
#pragma unroll
        for (int u = 0; u < 4; ++u) {
            const int r = rg + u * 32;
            const size_t row = (size_t)(rowQ0 + r) * QKV_N;
            const uint32_t so = qbase + ls_off + u * 32 * FAS;
            CP16(so,         qkvh + row + colQ + sg * 8);
            CP16(so + FTILE, qkvl + row + colQ + sg * 8);
        }
        CP_COMMIT();
    }
    LOADKV(0, 0);

    asm volatile("cp.async.wait_group 1;" ::: "memory");   // Q done
    __syncthreads();

    // ---- Q fragments to registers (warp's m16 rows = wid*16..+15)
    uint32_t qh[4][4], ql[4][4];
    {
        const uint32_t aoff = (uint32_t)((wid * 16 + (lane & 15)) * FAS + (lane >> 4) * 16);
#pragma unroll
        for (int ks = 0; ks < 4; ++ks) {
            LDSM4(qh[ks], qbase + aoff + ks * 32);
            LDSM4(ql[ks], qbase + FTILE + aoff + ks * 32);
        }
    }

    // K b-frag offsets (n = kv row), V trans offsets
    uint32_t koff[8];
#pragma unroll
    for (int p = 0; p < 8; ++p)
        koff[p] = (uint32_t)((p * 16 + ((lane >> 4) << 3) + (lane & 7)) * FAS
                             + ((lane >> 3) & 1) * 16);
    const int vg = lane >> 3;
    const uint32_t voff_r = (uint32_t)(((vg & 1) * 8 + (lane & 7)) * FAS + (vg >> 1) * 16);

    float O[8][4];
#pragma unroll
    for (int j = 0; j < 8; ++j)
#pragma unroll
        for (int r = 0; r < 4; ++r) O[j][r] = 0.0f;
    float m0 = -1e30f, m1 = -1e30f, l0 = 0.0f, l1 = 0.0f;

    const int r_lo = lane >> 2, c_lo = (lane & 3) * 2;
    const int row_loc0 = wid * 16 + r_lo;          // local q row (d0,d1)
    const int row_loc1 = row_loc0 + 8;             // (d2,d3)

    for (int kt = 0; kt <= qi; ++kt) {
        if (kt + 1 <= qi) {
            LOADKV(kt + 1, (kt + 1) & 1);
            asm volatile("cp.async.wait_group 1;" ::: "memory");
        } else {
            asm volatile("cp.async.wait_group 0;" ::: "memory");
        }
        __syncthreads();

        const uint32_t sKh = base + (kt & 1) * KVST;
        const uint32_t sKl = sKh + FTILE;
        const uint32_t sVh = sKh + 2 * FTILE;
        const uint32_t sVl = sKh + 3 * FTILE;

        // ---- S = Q K^T  (16 n8 frags per warp)
        float s[16][4];
#pragma unroll
        for (int j = 0; j < 16; ++j)
#pragma unroll
            for (int r = 0; r < 4; ++r) s[j][r] = 0.0f;

#pragma unroll
        for (int ks = 0; ks < 4; ++ks) {
#pragma unroll
            for (int p = 0; p < 8; ++p) {
                uint32_t kbh[4], kbl[4];
                LDSM4(kbh, sKh + koff[p] + ks * 32);
                LDSM4(kbl, sKl + koff[p] + ks * 32);
#pragma unroll
                for (int j = 0; j < 2; ++j) {
                    const int n8 = 2 * p + j;
                    MMA_BF16(s[n8], qh[ks], &kbh[j * 2]);
                    MMA_BF16(s[n8], qh[ks], &kbl[j * 2]);
                    MMA_BF16(s[n8], ql[ks], &kbh[j * 2]);
                }
            }
        }

        // ---- causal mask on diagonal tile
        if (kt == qi) {
#pragma unroll
            for (int n8 = 0; n8 < 16; ++n8) {
                const int c0 = n8 * 8 + c_lo;
                if (c0 > row_loc0)     s[n8][0] = -1e30f;
                if (c0 + 1 > row_loc0) s[n8][1] = -1e30f;
                if (c0 > row_loc1)     s[n8][2] = -1e30f;
                if (c0 + 1 > row_loc1) s[n8][3] = -1e30f;
            }
        }

        // ---- online softmax (rows r_lo, r_lo+8; 4-lane shfl groups)
        float mx0 = -1e30f, mx1 = -1e30f;
#pragma unroll
        for (int j = 0; j < 16; ++j) {
            mx0 = fmaxf(mx0, fmaxf(s[j][0], s[j][1]));
            mx1 = fmaxf(mx1, fmaxf(s[j][2], s[j][3]));
        }
#pragma unroll
        for (int off = 1; off <= 2; off <<= 1) {
            mx0 = fmaxf(mx0, __shfl_xor_sync(0xffffffffu, mx0, off, 32));
            mx1 = fmaxf(mx1, __shfl_xor_sync(0xffffffffu, mx1, off, 32));
        }
        const float mn0 = fmaxf(m0, mx0), mn1 = fmaxf(m1, mx1);
        const float cr0 = __expf(m0 - mn0), cr1 = __expf(m1 - mn1);
        float sum0 = 0.0f, sum1 = 0.0f;
#pragma unroll
        for (int j = 0; j < 16; ++j) {
            s[j][0] = __expf(s[j][0] - mn0); sum0 += s[j][0];
            s[j][1] = __expf(s[j][1] - mn0); sum0 += s[j][1];
            s[j][2] = __expf(s[j][2] - mn1); sum1 += s[j][2];
            s[j][3] = __expf(s[j][3] - mn1); sum1 += s[j][3];
        }
#pragma unroll
        for (int off = 1; off <= 2; off <<= 1) {
            sum0 += __shfl_xor_sync(0xffffffffu, sum0, off, 32);
            sum1 += __shfl_xor_sync(0xffffffffu, sum1, off, 32);
        }
        l0 = l0 * cr0 + sum0; l1 = l1 * cr1 + sum1;
        m0 = mn0; m1 = mn1;
#pragma unroll
        for (int j = 0; j < 8; ++j) {
            O[j][0] *= cr0; O[j][1] *= cr0; O[j][2] *= cr1; O[j][3] *= cr1;
        }

        // ---- O += P V  (pack P on the fly: C-frag pair -> A-frag, split hi/lo)
#pragma unroll
        for (int ks2 = 0; ks2 < 8; ++ks2) {
            uint32_t afh[4], afl[4];
            split2(s[2 * ks2][0],     s[2 * ks2][1],     afh[0], afl[0]);
            split2(s[2 * ks2][2],     s[2 * ks2][3],     afh[1], afl[1]);
            split2(s[2 * ks2 + 1][0], s[2 * ks2 + 1][1], afh[2], afl[2]);
            split2(s[2 * ks2 + 1][2], s[2 * ks2 + 1][3], afh[3], afl[3]);
            const uint32_t vrow = voff_r + ks2 * 16 * FAS;
#pragma unroll
            for (int j2 = 0; j2 < 4; ++j2) {
                uint32_t vbh[4], vbl[4];
                LDSM4T(vbh, sVh + vrow + j2 * 32);
                LDSM4T(vbl, sVl + vrow + j2 * 32);
#pragma unroll
                for (int j = 0; j < 2; ++j) {
                    const int n8 = 2 * j2 + j;
                    MMA_BF16(O[n8], afh, &vbh[j * 2]);
                    MMA_BF16(O[n8], afh, &vbl[j * 2]);
                    MMA_BF16(O[n8], afl, &vbh[j * 2]);
                }
            }
        }
        __syncthreads();
    }

    // ---- epilogue: normalize, split, store bf16 hi/lo
    const float inv0 = 1.0f / l0, inv1 = 1.0f / l1;
    const int grow0 = rowQ0 + row_loc0;
    const int grow1 = rowQ0 + row_loc1;
#pragma unroll
    for (int n8 = 0; n8 < 8; ++n8) {
        const int col = h * HEAD_DIM + n8 * 8 + c_lo;
        uint32_t hh, ll;
        split2(O[n8][0] * inv0, O[n8][1] * inv0, hh, ll);
        *(uint32_t*)(att_hi + (size_t)grow0 * D_MODEL + col) = hh;
        *(uint32_t*)(att_lo + (size_t)grow0 * D_MODEL + col) = ll;
        split2(O[n8][2] * inv1, O[n8][3] * inv1, hh, ll);
        *(uint32_t*)(att_hi + (size_t)grow1 * D_MODEL + col) = hh;
        *(uint32_t*)(att_lo + (size_t)grow1 * D_MODEL + col) = ll;
    }
#undef LOADKV
}

// ---------------------------------------------------------------------------
extern "C" void kernel_launch(void* const* d_in, const int* in_sizes, int n_in,
                              void* d_out, int out_size) {
    const float* x     = (const float*)d_in[0];
    const float* W_qkv = (const float*)d_in[1];
    const float* W_out = (const float*)d_in[2];
    float*       out   = (float*)d_out;

    __nv_bfloat16 *qh, *ql2, *xh, *xl, *wqh, *wql, *woh, *wol, *ath, *atl;
    cudaGetSymbolAddress((void**)&qh,  g_qkv_hi);
    cudaGetSymbolAddress((void**)&ql2, g_qkv_lo);
    cudaGetSymbolAddress((void**)&xh,  g_x_hi);
    cudaGetSymbolAddress((void**)&xl,  g_x_lo);
    cudaGetSymbolAddress((void**)&wqh, g_wqkv_hi);
    cudaGetSymbolAddress((void**)&wql, g_wqkv_lo);
    cudaGetSymbolAddress((void**)&woh, g_wout_hi);
    cudaGetSymbolAddress((void**)&wol, g_wout_lo);
    cudaGetSymbolAddress((void**)&ath, g_att_hi);
    cudaGetSymbolAddress((void**)&atl, g_att_lo);

    const int smem_gemm = 2 * STAGE_B;                 // 81920
    const int smem_attn = 2 * KVST + 2 * FTILE;        // 184320
    cudaFuncSetAttribute(bf16_gemm, cudaFuncAttributeMaxDynamicSharedMemorySize, smem_gemm);
    cudaFuncSetAttribute(flash_attn_tc, cudaFuncAttributeMaxDynamicSharedMemorySize, smem_attn);

    // prepare split operands (q pre-scale folded into W_qkv first 1024 cols)
    split_x_kernel<<<(M_ROWS * D_MODEL / 4 + 255) / 256, 256>>>((const float4*)x, xh, xl, M_ROWS * D_MODEL / 4);
    transpose_split<<<dim3(QKV_N / 32, D_MODEL / 32), dim3(32, 8)>>>(W_qkv, wqh, wql, D_MODEL, QKV_N, D_MODEL, 0.125f);
    transpose_split<<<dim3(D_MODEL / 32, D_MODEL / 32), dim3(32, 8)>>>(W_out, woh, wol, D_MODEL, D_MODEL, 0, 1.0f);

    // 1) qkv = x @ W_qkv  (split bf16 output)
    bf16_gemm<<<dim3(QKV_N / 128, M_ROWS / 128), 128, smem_gemm>>>(
        xh, xl, wqh, wql, nullptr, qh, ql2, M_ROWS, QKV_N, D_MODEL);

    // 2) causal flash attention (tensor cores)
    flash_attn_tc<<<dim3(T_SEQ / 128, B_SZ * N_HEADS), 256, smem_attn>>>(qh, ql2, ath, atl);

    // 3) out = att @ W_out  (fp32 output)
    bf16_gemm<<<dim3(D_MODEL / 128, M_ROWS / 128), 128, smem_gemm>>>(
        ath, atl, woh, wol, out, nullptr, nullptr, M_ROWS, D_MODEL, D_MODEL);
}